// round 1
// baseline (speedup 1.0000x reference)
#include <cuda_runtime.h>
#include <cuda_bf16.h>
#include <cstdint>

// Shapes (fixed by the problem)
#define BB      8
#define TIMES   288
#define NNODES  207
#define DD      64
#define TT      288      // tod modulus
#define FEA_IN  295      // 7 + 288

// out[b][t][n][e] = (relu(W1[dow] + W1[7+tod] + b1) @ W2 + b2)[e]  for all n.
// One block per (b,t). 122 MB of output writes dominate -> pure HBM-store kernel.
__global__ __launch_bounds__(256, 8)
void tememb_kernel(const int*   __restrict__ TE,
                   const float* __restrict__ W1,
                   const float* __restrict__ b1,
                   const float* __restrict__ W2,
                   const float* __restrict__ b2,
                   float*       __restrict__ out)
{
    const int bt  = blockIdx.x;     // 0 .. B*TIMES-1
    const int tid = threadIdx.x;    // 0 .. 255

    __shared__ float h[DD];
    __shared__ float o[DD];

    // TE is (B, TIMES, N, 2); we need node 0 only.
    const int* te = TE + (size_t)bt * (NNODES * 2);

    if (tid < DD) {
        // indices (randint is nonnegative; plain % is fine, but guard anyway)
        int dow = te[0] % 7;  if (dow < 0) dow += 7;
        int tod = te[1] % TT; if (tod < 0) tod += TT;

        float v = W1[dow * DD + tid] + W1[(7 + tod) * DD + tid] + b1[tid];
        h[tid] = v > 0.f ? v : 0.f;
    }
    __syncthreads();

    if (tid < DD) {
        float acc = b2[tid];
        #pragma unroll
        for (int d = 0; d < DD; ++d)
            acc = fmaf(h[d], W2[d * DD + tid], acc);   // W2 column access, coalesced across tid
        o[tid] = acc;
    }
    __syncthreads();

    // Broadcast the 64-float result to all 207 nodes.
    // Row for this (b,t) is NNODES*DD = 13248 contiguous floats = 3312 float4.
    // (tid + k*256) % 16 == tid % 16, so each thread's source float4 is fixed.
    const float4 v4 = reinterpret_cast<const float4*>(o)[tid & 15];
    float4* dst = reinterpret_cast<float4*>(out) + (size_t)bt * (NNODES * DD / 4);

    constexpr int NV = NNODES * DD / 4;   // 3312
    #pragma unroll 4
    for (int j = tid; j < NV; j += 256)
        dst[j] = v4;
}

extern "C" void kernel_launch(void* const* d_in, const int* in_sizes, int n_in,
                              void* d_out, int out_size)
{
    // metadata order: TE (int32), W1, b1, W2, b2, [T scalar — unused]
    const int*   TE = (const int*)  d_in[0];
    const float* W1 = (const float*)d_in[1];
    const float* b1 = (const float*)d_in[2];
    const float* W2 = (const float*)d_in[3];
    const float* b2 = (const float*)d_in[4];
    float* out = (float*)d_out;

    tememb_kernel<<<BB * TIMES, 256>>>(TE, W1, b1, W2, b2, out);
}